// round 15
// baseline (speedup 1.0000x reference)
#include <cuda_runtime.h>
#include <cuda_fp16.h>
#include <math.h>
#include <stdint.h>

#define B_SZ    2
#define T_SEQ   2048
#define D_MODEL 2048
#define N_HEADS 16
#define N_KV    4
#define HD      128
#define KDIM    2048
#define MROWS   (B_SZ * T_SEQ)          // 4096

#define QSCALE  (0.08838834764831845f * 1.4426950408889634f)

// ---------------- scratch (static device globals; no allocs) ----------------
__device__ __half g_xF[(size_t)MROWS * KDIM];
__device__ __half g_wF[(size_t)3072 * KDIM];    // wq|wk (row-permuted) | wv
__device__ __half g_woF[(size_t)2048 * KDIM];
__device__ __half g_aF[(size_t)MROWS * KDIM];

__device__ __half g_qF[(size_t)B_SZ * N_HEADS * T_SEQ * HD];  // post-RoPE (permuted dims)
__device__ __half g_kF[(size_t)B_SZ * N_KV * T_SEQ * HD];
__device__ __half g_vF[(size_t)B_SZ * N_KV * T_SEQ * HD];
__device__ float2 g_rope[(size_t)T_SEQ * 64];                 // (cos, sin) per (pos, freq)

// ---------------- helpers ----------------
__device__ __forceinline__ uint32_t smem_to_u32(const void* p) {
    uint32_t a;
    asm("{ .reg .u64 t; cvta.to.shared.u64 t, %1; cvt.u32.u64 %0, t; }" : "=r"(a) : "l"(p));
    return a;
}
#define SW128(off) ((off) ^ (((off) >> 3) & 0x70))

__device__ __forceinline__ void cp16(uint32_t saddr, const void* g) {
    asm volatile("cp.async.cg.shared.global [%0], [%1], 16;\n" :: "r"(saddr), "l"(g));
}
#define LDSM_X4(r, a) \
    asm volatile("ldmatrix.sync.aligned.m8n8.x4.shared.b16 {%0,%1,%2,%3}, [%4];" \
        : "=r"((r)[0]), "=r"((r)[1]), "=r"((r)[2]), "=r"((r)[3]) : "r"(a))
#define LDSM_X4_T(r, a) \
    asm volatile("ldmatrix.sync.aligned.m8n8.x4.trans.shared.b16 {%0,%1,%2,%3}, [%4];" \
        : "=r"((r)[0]), "=r"((r)[1]), "=r"((r)[2]), "=r"((r)[3]) : "r"(a))
#define MMA16816(c, a, b0, b1) \
    asm volatile("mma.sync.aligned.m16n8k16.row.col.f32.f16.f16.f32 " \
        "{%0,%1,%2,%3}, {%4,%5,%6,%7}, {%8,%9}, {%0,%1,%2,%3};" \
        : "+f"((c)[0]), "+f"((c)[1]), "+f"((c)[2]), "+f"((c)[3]) \
        : "r"((a)[0]), "r"((a)[1]), "r"((a)[2]), "r"((a)[3]), "r"(b0), "r"(b1))

__device__ __forceinline__ uint32_t packh(float a, float b) {
    __half2 t = __floats2half2_rn(a, b);
    return reinterpret_cast<uint32_t&>(t);
}

// ---------------- RoPE table: (cos, sin) for pos x freq ----------------
__global__ void rope_table()
{
    int idx = blockIdx.x * blockDim.x + threadIdx.x;
    if (idx >= T_SEQ * 64) return;
    int tq = idx >> 6, j = idx & 63;
    float inv = __expf(-((float)j / 64.0f) * 13.815510557964274f);
    float s, c;
    sincosf((float)tq * inv, &s, &c);
    g_rope[idx] = make_float2(c, s);
}

// ---------------- fused fp32 -> fp16 conversion (wq/wk rows permuted) -----------
// Permutation: within each head, out-dim pairs (2j, 2j+1) = orig (j, j+64).
#define CV_X   2097152                       // float4 counts
#define CV_WQ  (CV_X  + 1048576)
#define CV_WK  (CV_WQ + 262144)
#define CV_WV  (CV_WK + 262144)
#define CV_WO  (CV_WV + 1048576)             // 4718592 total

__global__ void convert_all(const float* __restrict__ x,  const float* __restrict__ wq,
                            const float* __restrict__ wk, const float* __restrict__ wv,
                            const float* __restrict__ wo,
                            __half* __restrict__ xF, __half* __restrict__ wF,
                            __half* __restrict__ woF)
{
    int i = blockIdx.x * blockDim.x + threadIdx.x;
    if (i >= CV_WO) return;
    const float* src; __half* dst; int off; int doff;
    if      (i < CV_X)  { src = x;  dst = xF;  off = i; doff = off; }
    else if (i < CV_WQ) {
        src = wq; dst = wF; off = i - CV_X;
        int row = off >> 9, cin = off & 511;
        int j = row & 127;
        int pj = (j < 64) ? (2 * j) : (2 * (j - 64) + 1);
        doff = (((row & ~127) | pj) << 9) | cin;
    }
    else if (i < CV_WK) {
        src = wk; dst = wF + (size_t)2048 * KDIM; off = i - CV_WQ;
        int row = off >> 9, cin = off & 511;
        int j = row & 127;
        int pj = (j < 64) ? (2 * j) : (2 * (j - 64) + 1);
        doff = (((row & ~127) | pj) << 9) | cin;
    }
    else if (i < CV_WV) { src = wv; dst = wF + (size_t)2560 * KDIM; off = i - CV_WK; doff = off; }
    else                { src = wo; dst = woF; off = i - CV_WV; doff = off; }
    float4 v = ((const float4*)src)[off];
    ((__half2*)dst)[2 * doff]     = __floats2half2_rn(v.x, v.y);
    ((__half2*)dst)[2 * doff + 1] = __floats2half2_rn(v.z, v.w);
}

// ---------------- persistent fp16 GEMM: C = A @ B^T, tile 128x128, 2 CTAs/SM ------
// MODE 0: C row-major fp32 (N=2048). MODE 1: QKV scatter + fused RoPE -> qF/kF/vF.
#define OFF_A  0
#define OFF_B  16384
#define STAGE_BYTES 32768
#define GEMM_SMEM (3 * STAGE_BYTES)     // 98304
#define GEMM_GRID 296

template<int MODE>
__global__ __launch_bounds__(256, 2)
void gemm_fp16(const __half* __restrict__ Af, const __half* __restrict__ Bf,
               float* __restrict__ C, int ntn, int ntiles)
{
    extern __shared__ __align__(1024) char smem[];
    const uint32_t sb = smem_to_u32(smem);
    const int tid  = threadIdx.x;
    const int lane = tid & 31;
    const int wid  = tid >> 5;
    const int warp_m = (wid & 3) * 32;
    const int warp_n = (wid >> 2) * 64;

    const int lrow = (lane & 7) + ((lane >> 3) & 1) * 8;
    const uint32_t abase = (uint32_t)((warp_m + lrow) * 128);
    const uint32_t bbase = (uint32_t)((warp_n + lrow) * 128);

    for (int tile = blockIdx.x; tile < ntiles; tile += GEMM_GRID) {
        const int bm0 = (tile / ntn) * 128;
        const int bn0 = (tile % ntn) * 128;

        float acc[2][8][4];
        #pragma unroll
        for (int mt = 0; mt < 2; mt++)
            #pragma unroll
            for (int nt = 0; nt < 8; nt++)
                #pragma unroll
                for (int i = 0; i < 4; i++) acc[mt][nt][i] = 0.f;

        auto load_chunk = [&](int c) {
            uint32_t st = sb + (uint32_t)(c % 3) * STAGE_BYTES;
            int k0 = c * 64;
            #pragma unroll
            for (int j = 0; j < 4; j++) {
                int i = tid + j * 256;
                int row = i >> 3, cb = (i & 7) * 16;
                uint32_t so = SW128((uint32_t)(row * 128 + cb));
                cp16(st + OFF_A + so, (const char*)Af + ((size_t)(bm0 + row) * KDIM + k0) * 2 + cb);
                cp16(st + OFF_B + so, (const char*)Bf + ((size_t)(bn0 + row) * KDIM + k0) * 2 + cb);
            }
            asm volatile("cp.async.commit_group;\n");
        };

        load_chunk(0);
        load_chunk(1);

        const int NC = KDIM / 64;
        for (int c = 0; c < NC; c++) {
            if (c == NC - 1) asm volatile("cp.async.wait_group 0;\n");
            else             asm volatile("cp.async.wait_group 1;\n");
            __syncthreads();
            if (c + 2 < NC) load_chunk(c + 2);

            uint32_t st = sb + (uint32_t)(c % 3) * STAGE_BYTES;
            #pragma unroll
            for (int ks = 0; ks < 4; ks++) {
                uint32_t ah[2][4], bh[4][4];
                int lcb = ks * 32 + (lane >> 4) * 16;
                #pragma unroll
                for (int mt = 0; mt < 2; mt++)
                    LDSM_X4(ah[mt], st + OFF_A + SW128(abase + mt * 2048 + lcb));
                #pragma unroll
                for (int nt = 0; nt < 4; nt++)
                    LDSM_X4(bh[nt], st + OFF_B + SW128(bbase + nt * 2048 + lcb));
                #pragma unroll
                for (int mt = 0; mt < 2; mt++) {
                    #pragma unroll
                    for (int nt4 = 0; nt4 < 4; nt4++) {
                        MMA16816(acc[mt][2*nt4],   ah[mt], bh[nt4][0], bh[nt4][2]);
                        MMA16816(acc[mt][2*nt4+1], ah[mt], bh[nt4][1], bh[nt4][3]);
                    }
                }
            }
        }

        const int rbase = bm0 + warp_m + (lane >> 2);
        const int cbase = bn0 + warp_n + (lane & 3) * 2;
        #pragma unroll
        for (int mt = 0; mt < 2; mt++) {
            #pragma unroll
            for (int hh = 0; hh < 2; hh++) {
                int row = rbase + mt * 16 + hh * 8;
                #pragma unroll
                for (int nt = 0; nt < 8; nt++) {
                    int col = cbase + nt * 8;
                    float2 v = make_float2(acc[mt][nt][2*hh], acc[mt][nt][2*hh+1]);
                    if (MODE == 0) {
                        *(float2*)&C[(size_t)row * 2048 + col] = v;
                    } else {
                        int b = row >> 11, tq = row & (T_SEQ - 1), d = col & 127;
                        if (col < 2048) {
                            int h = col >> 7;
                            float2 cs = g_rope[tq * 64 + (d >> 1)];
                            float o1 = (v.x * cs.x - v.y * cs.y) * QSCALE;
                            float o2 = (v.y * cs.x + v.x * cs.y) * QSCALE;
                            *(uint32_t*)(g_qF + (((size_t)(b * N_HEADS + h) * T_SEQ + tq) * HD + d)) = packh(o1, o2);
                        } else if (col < 2560) {
                            int h = (col - 2048) >> 7;
                            float2 cs = g_rope[tq * 64 + (d >> 1)];
                            float o1 = v.x * cs.x - v.y * cs.y;
                            float o2 = v.y * cs.x + v.x * cs.y;
                            *(uint32_t*)(g_kF + (((size_t)(b * N_KV + h) * T_SEQ + tq) * HD + d)) = packh(o1, o2);
                        } else {
                            int h = (col - 2560) >> 7;
                            *(uint32_t*)(g_vF + (((size_t)(b * N_KV + h) * T_SEQ + tq) * HD + d)) = packh(v.x, v.y);
                        }
                    }
                }
            }
        }
        __syncthreads();   // stages safe before next tile's prologue
    }
}

// ---------------- tensor-core flash attention (fp16, BN=128, base-2 softmax) ------
#define ATT_Q 0
#define ATT_ST0 32768
#define ATT_STAGE 65536
#define ATT_K 0
#define ATT_V 32768
#define ATT_SMEM (ATT_ST0 + 3 * ATT_STAGE)   // 229376

__device__ __forceinline__ uint32_t swz256(int row, int cb) {
    return (uint32_t)(row * 256 + ((cb ^ (row & 7)) << 4));
}

__global__ __launch_bounds__(256, 1)
void attn_mma(const __half* __restrict__ qf, const __half* __restrict__ kf,
              const __half* __restrict__ vf, __half* __restrict__ oF)
{
    extern __shared__ __align__(1024) char smem[];
    const uint32_t sb = smem_to_u32(smem);
    const int tid  = threadIdx.x;
    const int w    = tid >> 5;
    const int lane = tid & 31;
    const int qt   = (gridDim.x - 1) - blockIdx.x;
    const int bh   = blockIdx.y;
    const int b    = bh >> 4;
    const int h    = bh & 15;
    const int kvh  = h >> 2;

    const size_t qoff = ((size_t)bh * T_SEQ + (size_t)qt * 128) * HD;
    const size_t koff = (size_t)(b * N_KV + kvh) * T_SEQ * HD;

    const int r4 = lane >> 2;
    const int lrow = (lane & 7) + ((lane >> 3) & 1) * 8;
    const int lhi  = lane >> 4;

    #pragma unroll
    for (int j = 0; j < 8; j++) {
        int i = tid + j * 256;
        int row = i >> 4, cb = i & 15;
        cp16(sb + ATT_Q + swz256(row, cb),
             (const char*)qf + (qoff + (size_t)row * HD) * 2 + cb * 16);
    }
    asm volatile("cp.async.commit_group;\n");

    auto load_stage = [&](int kt) {
        uint32_t st = sb + ATT_ST0 + (uint32_t)(kt % 3) * ATT_STAGE;
        size_t base = (koff + (size_t)kt * 128 * HD) * 2;
        #pragma unroll
        for (int j = 0; j < 8; j++) {
            int i = tid + j * 256;
            int row = i >> 4, cb = i & 15;
            uint32_t so = swz256(row, cb);
            size_t go = base + (size_t)row * 256 + cb * 16;
            cp16(st + ATT_K + so, (const char*)kf + go);
            cp16(st + ATT_V + so, (const char*)vf + go);
        }
        asm volatile("cp.async.commit_group;\n");
    };

    const int nkt = qt + 1;
    load_stage(0);
    if (nkt > 1) load_stage(1);

    float acc[16][4];
    #pragma unroll
    for (int nt = 0; nt < 16; nt++)
        #pragma unroll
        for (int i = 0; i < 4; i++) acc[nt][i] = 0.f;
    float m0 = -1e30f, m1 = -1e30f, l0 = 0.f, l1 = 0.f;

    const int qrow0 = qt * 128 + 16 * w + r4;
    const uint32_t qbase = (uint32_t)((16 * w + lrow) * 256);
    const uint32_t krow  = (uint32_t)(lrow * 256);
    const int rmask = lrow & 7;

    for (int kt = 0; kt < nkt; kt++) {
        if (kt == nkt - 1) asm volatile("cp.async.wait_group 0;\n");
        else               asm volatile("cp.async.wait_group 1;\n");
        __syncthreads();
        if (kt + 2 < nkt) load_stage(kt + 2);

        int kvbase = kt * 128;
        uint32_t st = sb + ATT_ST0 + (uint32_t)(kt % 3) * ATT_STAGE;

        float sacc[16][4];
        #pragma unroll
        for (int nt = 0; nt < 16; nt++)
            #pragma unroll
            for (int i = 0; i < 4; i++) sacc[nt][i] = 0.f;

        #pragma unroll
        for (int ks = 0; ks < 8; ks++) {
            int cb = 2 * ks + lhi;
            uint32_t q4[4];
            LDSM_X4(q4, sb + ATT_Q + qbase + ((uint32_t)(cb ^ rmask) << 4));
            #pragma unroll
            for (int nt2 = 0; nt2 < 8; nt2++) {
                uint32_t k4[4];
                LDSM_X4(k4, st + ATT_K + krow + nt2 * 4096 + ((uint32_t)(cb ^ rmask) << 4));
                MMA16816(sacc[2*nt2],   q4, k4[0], k4[2]);
                MMA16816(sacc[2*nt2+1], q4, k4[1], k4[3]);
            }
        }

        if (kvbase + 127 > qrow0) {
            #pragma unroll
            for (int nt = 0; nt < 16; nt++) {
                int col = kvbase + 8 * nt + (lane & 3) * 2;
                if (col     > qrow0)     sacc[nt][0] = -1e30f;
                if (col + 1 > qrow0)     sacc[nt][1] = -1e30f;
                if (col     > qrow0 + 8) sacc[nt][2] = -1e30f;
                if (col + 1 > qrow0 + 8) sacc[nt][3] = -1e30f;
            }
        }

        float ml0 = -1e30f, ml1 = -1e30f;
        #pragma unroll
        for (int nt = 0; nt < 16; nt++) {
            ml0 = fmaxf(ml0, fmaxf(sacc[nt][0], sacc[nt][1]));
            ml1 = fmaxf(ml1, fmaxf(sacc[nt][2], sacc[nt][3]));
        }
        ml0 = fmaxf(ml0, __shfl_xor_sync(0xffffffffu, ml0, 1));
        ml0 = fmaxf(ml0, __shfl_xor_sync(0xffffffffu, ml0, 2));
        ml1 = fmaxf(ml1, __shfl_xor_sync(0xffffffffu, ml1, 1));
        ml1 = fmaxf(ml1, __shfl_xor_sync(0xffffffffu, ml1, 2));
        float mn0 = fmaxf(m0, ml0), mn1 = fmaxf(m1, ml1);
        float c0 = exp2f(m0 - mn0), c1 = exp2f(m1 - mn1);
        float ps0 = 0.f, ps1 = 0.f;
        #pragma unroll
        for (int nt = 0; nt < 16; nt++) {
            sacc[nt][0] = exp2f(sacc[nt][0] - mn0);
            sacc[nt][1] = exp2f(sacc[nt][1] - mn0);
            sacc[nt][2] = exp2f(sacc[nt][2] - mn1);
            sacc[nt][3] = exp2f(sacc[nt][3] - mn1);
            ps0 += sacc[nt][0] + sacc[nt][1];
            ps1 += sacc[nt][2] + sacc[nt][3];
        }
        ps0 += __shfl_xor_sync(0xffffffffu, ps0, 1);
        ps0 += __shfl_xor_sync(0xffffffffu, ps0, 2);
        ps1 += __shfl_xor_sync(0xffffffffu, ps1, 1);
        ps1 += __shfl_xor_sync(0xffffffffu, ps1, 2);
        l0 = l0 * c0 + ps0;
        l1 = l1 * c1 + ps1;
        m0 = mn0; m1 = mn1;
        #pragma unroll
        for (int nt = 0; nt < 16; nt++) {
            acc[nt][0] *= c0; acc[nt][1] *= c0;
            acc[nt][2] *= c1; acc[nt][3] *= c1;
        }

        uint32_t ph[8][4];
        #pragma unroll
        for (int j = 0; j < 8; j++) {
            #pragma unroll
            for (int half = 0; half < 2; half++) {
                ph[j][2*half]   = packh(sacc[2*j+half][0], sacc[2*j+half][1]);
                ph[j][2*half+1] = packh(sacc[2*j+half][2], sacc[2*j+half][3]);
            }
        }

        #pragma unroll
        for (int j = 0; j < 8; j++) {
            uint32_t vrow = st + ATT_V + krow + j * 4096;
            #pragma unroll
            for (int dt = 0; dt < 8; dt++) {
                int cb = 2 * dt + lhi;
                uint32_t v4[4];
                LDSM_X4_T(v4, vrow + ((uint32_t)(cb ^ rmask) << 4));
                MMA16816(acc[2*dt],   ph[j], v4[0], v4[1]);
                MMA16816(acc[2*dt+1], ph[j], v4[2], v4[3]);
            }
        }
    }

    float i0 = 1.f / l0, i1 = 1.f / l1;
    const int trow0 = qt * 128 + 16 * w + r4;
    const size_t orow0 = (size_t)(b * T_SEQ + trow0) * 2048 + h * 128;
    const size_t orow1 = orow0 + 8 * 2048;
    #pragma unroll
    for (int nt = 0; nt < 16; nt++) {
        int d = 8 * nt + (lane & 3) * 2;
        *(uint32_t*)&oF[orow0 + d] = packh(acc[nt][0] * i0, acc[nt][1] * i0);
        *(uint32_t*)&oF[orow1 + d] = packh(acc[nt][2] * i1, acc[nt][3] * i1);
    }
}

// ---------------- launch ----------------
extern "C" void kernel_launch(void* const* d_in, const int* in_sizes, int n_in,
                              void* d_out, int out_size)
{
    const float* x   = (const float*)d_in[0];
    const float* w_q = (const float*)d_in[1];
    const float* w_k = (const float*)d_in[2];
    const float* w_v = (const float*)d_in[3];
    const float* w_o = (const float*)d_in[4];
    float* out = (float*)d_out;

    __half *xF, *wF, *woF, *aF, *qF, *kF, *vF;
    cudaGetSymbolAddress((void**)&xF,  g_xF);
    cudaGetSymbolAddress((void**)&wF,  g_wF);
    cudaGetSymbolAddress((void**)&woF, g_woF);
    cudaGetSymbolAddress((void**)&aF,  g_aF);
    cudaGetSymbolAddress((void**)&qF,  g_qF);
    cudaGetSymbolAddress((void**)&kF,  g_kF);
    cudaGetSymbolAddress((void**)&vF,  g_vF);

    // RoPE cos/sin table + fused input conversion (wq/wk rows permuted)
    rope_table<<<(T_SEQ * 64 + 255) / 256, 256>>>();
    convert_all<<<(CV_WO + 255) / 256, 256>>>(x, w_q, w_k, w_v, w_o, xF, wF, woF);

    cudaFuncSetAttribute(gemm_fp16<0>, cudaFuncAttributeMaxDynamicSharedMemorySize, GEMM_SMEM);
    cudaFuncSetAttribute(gemm_fp16<1>, cudaFuncAttributeMaxDynamicSharedMemorySize, GEMM_SMEM);

    // persistent fused QKV projection + RoPE epilogue -> qF/kF/vF
    gemm_fp16<1><<<GEMM_GRID, 256, GEMM_SMEM>>>(xF, wF, nullptr, 3072 / 128, (3072 / 128) * (MROWS / 128));

    // tensor-core attention (BN=128) -> g_aF
    cudaFuncSetAttribute(attn_mma, cudaFuncAttributeMaxDynamicSharedMemorySize, ATT_SMEM);
    attn_mma<<<dim3(T_SEQ / 128, B_SZ * N_HEADS), 256, ATT_SMEM>>>(qF, kF, vF, aF);

    // persistent O projection
    gemm_fp16<0><<<GEMM_GRID, 256, GEMM_SMEM>>>(aF, woF, out, 2048 / 128, (2048 / 128) * (MROWS / 128));
}

// round 16
// speedup vs baseline: 1.0444x; 1.0444x over previous
#include <cuda_runtime.h>
#include <cuda_fp16.h>
#include <math.h>
#include <stdint.h>

#define B_SZ    2
#define T_SEQ   2048
#define D_MODEL 2048
#define N_HEADS 16
#define N_KV    4
#define HD      128
#define KDIM    2048
#define MROWS   (B_SZ * T_SEQ)          // 4096

#define QSCALE  (0.08838834764831845f * 1.4426950408889634f)

// ---------------- scratch (static device globals; no allocs) ----------------
__device__ __half g_xF[(size_t)MROWS * KDIM];
__device__ __half g_wF[(size_t)3072 * KDIM];    // wq|wk (row-permuted) | wv
__device__ __half g_woF[(size_t)2048 * KDIM];
__device__ __half g_aF[(size_t)MROWS * KDIM];

__device__ __half g_qF[(size_t)B_SZ * N_HEADS * T_SEQ * HD];  // post-RoPE (permuted dims)
__device__ __half g_kF[(size_t)B_SZ * N_KV * T_SEQ * HD];
__device__ __half g_vF[(size_t)B_SZ * N_KV * T_SEQ * HD];
__device__ float2 g_rope[(size_t)T_SEQ * 64];                 // (cos, sin) per (pos, freq)

// ---------------- helpers ----------------
__device__ __forceinline__ uint32_t smem_to_u32(const void* p) {
    uint32_t a;
    asm("{ .reg .u64 t; cvta.to.shared.u64 t, %1; cvt.u32.u64 %0, t; }" : "=r"(a) : "l"(p));
    return a;
}
#define SW128(off) ((off) ^ (((off) >> 3) & 0x70))

__device__ __forceinline__ void cp16(uint32_t saddr, const void* g) {
    asm volatile("cp.async.cg.shared.global [%0], [%1], 16;\n" :: "r"(saddr), "l"(g));
}
#define LDSM_X4(r, a) \
    asm volatile("ldmatrix.sync.aligned.m8n8.x4.shared.b16 {%0,%1,%2,%3}, [%4];" \
        : "=r"((r)[0]), "=r"((r)[1]), "=r"((r)[2]), "=r"((r)[3]) : "r"(a))
#define LDSM_X4_T(r, a) \
    asm volatile("ldmatrix.sync.aligned.m8n8.x4.trans.shared.b16 {%0,%1,%2,%3}, [%4];" \
        : "=r"((r)[0]), "=r"((r)[1]), "=r"((r)[2]), "=r"((r)[3]) : "r"(a))
#define MMA16816(c, a, b0, b1) \
    asm volatile("mma.sync.aligned.m16n8k16.row.col.f32.f16.f16.f32 " \
        "{%0,%1,%2,%3}, {%4,%5,%6,%7}, {%8,%9}, {%0,%1,%2,%3};" \
        : "+f"((c)[0]), "+f"((c)[1]), "+f"((c)[2]), "+f"((c)[3]) \
        : "r"((a)[0]), "r"((a)[1]), "r"((a)[2]), "r"((a)[3]), "r"(b0), "r"(b1))

__device__ __forceinline__ uint32_t packh(float a, float b) {
    __half2 t = __floats2half2_rn(a, b);
    return reinterpret_cast<uint32_t&>(t);
}

// ---------------- RoPE table: (cos, sin) for pos x freq ----------------
__global__ void rope_table()
{
    int idx = blockIdx.x * blockDim.x + threadIdx.x;
    if (idx >= T_SEQ * 64) return;
    int tq = idx >> 6, j = idx & 63;
    float inv = __expf(-((float)j / 64.0f) * 13.815510557964274f);
    float s, c;
    sincosf((float)tq * inv, &s, &c);
    g_rope[idx] = make_float2(c, s);
}

// ---------------- fused fp32 -> fp16 conversion (wq/wk rows permuted) -----------
// Permutation: within each head, out-dim pairs (2j, 2j+1) = orig (j, j+64).
#define CV_X   2097152                       // float4 counts
#define CV_WQ  (CV_X  + 1048576)
#define CV_WK  (CV_WQ + 262144)
#define CV_WV  (CV_WK + 262144)
#define CV_WO  (CV_WV + 1048576)             // 4718592 total

__global__ void convert_all(const float* __restrict__ x,  const float* __restrict__ wq,
                            const float* __restrict__ wk, const float* __restrict__ wv,
                            const float* __restrict__ wo,
                            __half* __restrict__ xF, __half* __restrict__ wF,
                            __half* __restrict__ woF)
{
    int i = blockIdx.x * blockDim.x + threadIdx.x;
    if (i >= CV_WO) return;
    const float* src; __half* dst; int off; int doff;
    if      (i < CV_X)  { src = x;  dst = xF;  off = i; doff = off; }
    else if (i < CV_WQ) {
        src = wq; dst = wF; off = i - CV_X;
        int row = off >> 9, cin = off & 511;
        int j = row & 127;
        int pj = (j < 64) ? (2 * j) : (2 * (j - 64) + 1);
        doff = (((row & ~127) | pj) << 9) | cin;
    }
    else if (i < CV_WK) {
        src = wk; dst = wF + (size_t)2048 * KDIM; off = i - CV_WQ;
        int row = off >> 9, cin = off & 511;
        int j = row & 127;
        int pj = (j < 64) ? (2 * j) : (2 * (j - 64) + 1);
        doff = (((row & ~127) | pj) << 9) | cin;
    }
    else if (i < CV_WV) { src = wv; dst = wF + (size_t)2560 * KDIM; off = i - CV_WK; doff = off; }
    else                { src = wo; dst = woF; off = i - CV_WV; doff = off; }
    float4 v = ((const float4*)src)[off];
    ((__half2*)dst)[2 * doff]     = __floats2half2_rn(v.x, v.y);
    ((__half2*)dst)[2 * doff + 1] = __floats2half2_rn(v.z, v.w);
}

// ---------------- fp16 GEMM: C = A @ B^T, tile 128x128, 2 CTAs/SM ----------------
// MODE 0: C row-major fp32 (N=2048). MODE 1: QKV scatter + fused RoPE -> qF/kF/vF.
#define OFF_A  0
#define OFF_B  16384
#define STAGE_BYTES 32768
#define GEMM_SMEM (3 * STAGE_BYTES)     // 98304

template<int MODE>
__global__ __launch_bounds__(256, 2)
void gemm_fp16(const __half* __restrict__ Af, const __half* __restrict__ Bf,
               float* __restrict__ C)
{
    extern __shared__ __align__(1024) char smem[];
    const uint32_t sb = smem_to_u32(smem);
    const int tid  = threadIdx.x;
    const int lane = tid & 31;
    const int wid  = tid >> 5;
    const int warp_m = (wid & 3) * 32;
    const int warp_n = (wid >> 2) * 64;
    const int bm0 = blockIdx.y * 128;
    const int bn0 = blockIdx.x * 128;

    float acc[2][8][4];
    #pragma unroll
    for (int mt = 0; mt < 2; mt++)
        #pragma unroll
        for (int nt = 0; nt < 8; nt++)
            #pragma unroll
            for (int i = 0; i < 4; i++) acc[mt][nt][i] = 0.f;

    auto load_chunk = [&](int c) {
        uint32_t st = sb + (uint32_t)(c % 3) * STAGE_BYTES;
        int k0 = c * 64;
        #pragma unroll
        for (int j = 0; j < 4; j++) {
            int i = tid + j * 256;
            int row = i >> 3, cb = (i & 7) * 16;
            uint32_t so = SW128((uint32_t)(row * 128 + cb));
            cp16(st + OFF_A + so, (const char*)Af + ((size_t)(bm0 + row) * KDIM + k0) * 2 + cb);
            cp16(st + OFF_B + so, (const char*)Bf + ((size_t)(bn0 + row) * KDIM + k0) * 2 + cb);
        }
        asm volatile("cp.async.commit_group;\n");
    };

    load_chunk(0);
    load_chunk(1);

    const int lrow = (lane & 7) + ((lane >> 3) & 1) * 8;
    const uint32_t abase = (uint32_t)((warp_m + lrow) * 128);
    const uint32_t bbase = (uint32_t)((warp_n + lrow) * 128);

    const int NC = KDIM / 64;
    for (int c = 0; c < NC; c++) {
        if (c == NC - 1) asm volatile("cp.async.wait_group 0;\n");
        else             asm volatile("cp.async.wait_group 1;\n");
        __syncthreads();
        if (c + 2 < NC) load_chunk(c + 2);

        uint32_t st = sb + (uint32_t)(c % 3) * STAGE_BYTES;
        #pragma unroll
        for (int ks = 0; ks < 4; ks++) {
            uint32_t ah[2][4], bh[4][4];
            int lcb = ks * 32 + (lane >> 4) * 16;
            #pragma unroll
            for (int mt = 0; mt < 2; mt++)
                LDSM_X4(ah[mt], st + OFF_A + SW128(abase + mt * 2048 + lcb));
            #pragma unroll
            for (int nt = 0; nt < 4; nt++)
                LDSM_X4(bh[nt], st + OFF_B + SW128(bbase + nt * 2048 + lcb));
            #pragma unroll
            for (int mt = 0; mt < 2; mt++) {
                #pragma unroll
                for (int nt4 = 0; nt4 < 4; nt4++) {
                    MMA16816(acc[mt][2*nt4],   ah[mt], bh[nt4][0], bh[nt4][2]);
                    MMA16816(acc[mt][2*nt4+1], ah[mt], bh[nt4][1], bh[nt4][3]);
                }
            }
        }
    }

    const int rbase = bm0 + warp_m + (lane >> 2);
    const int cbase = bn0 + warp_n + (lane & 3) * 2;
    #pragma unroll
    for (int mt = 0; mt < 2; mt++) {
        #pragma unroll
        for (int hh = 0; hh < 2; hh++) {
            int row = rbase + mt * 16 + hh * 8;
            #pragma unroll
            for (int nt = 0; nt < 8; nt++) {
                int col = cbase + nt * 8;
                float2 v = make_float2(acc[mt][nt][2*hh], acc[mt][nt][2*hh+1]);
                if (MODE == 0) {
                    *(float2*)&C[(size_t)row * 2048 + col] = v;
                } else {
                    int b = row >> 11, tq = row & (T_SEQ - 1), d = col & 127;
                    if (col < 2048) {
                        int h = col >> 7;
                        float2 cs = g_rope[tq * 64 + (d >> 1)];
                        float o1 = (v.x * cs.x - v.y * cs.y) * QSCALE;
                        float o2 = (v.y * cs.x + v.x * cs.y) * QSCALE;
                        *(uint32_t*)(g_qF + (((size_t)(b * N_HEADS + h) * T_SEQ + tq) * HD + d)) = packh(o1, o2);
                    } else if (col < 2560) {
                        int h = (col - 2048) >> 7;
                        float2 cs = g_rope[tq * 64 + (d >> 1)];
                        float o1 = v.x * cs.x - v.y * cs.y;
                        float o2 = v.y * cs.x + v.x * cs.y;
                        *(uint32_t*)(g_kF + (((size_t)(b * N_KV + h) * T_SEQ + tq) * HD + d)) = packh(o1, o2);
                    } else {
                        int h = (col - 2560) >> 7;
                        *(uint32_t*)(g_vF + (((size_t)(b * N_KV + h) * T_SEQ + tq) * HD + d)) = packh(v.x, v.y);
                    }
                }
            }
        }
    }
}

// ---------------- tensor-core flash attention (fp16, BN=128, base-2 softmax) ------
#define ATT_Q 0
#define ATT_ST0 32768
#define ATT_STAGE 65536
#define ATT_K 0
#define ATT_V 32768
#define ATT_SMEM (ATT_ST0 + 3 * ATT_STAGE)   // 229376

__device__ __forceinline__ uint32_t swz256(int row, int cb) {
    return (uint32_t)(row * 256 + ((cb ^ (row & 7)) << 4));
}

__global__ __launch_bounds__(256, 1)
void attn_mma(const __half* __restrict__ qf, const __half* __restrict__ kf,
              const __half* __restrict__ vf, __half* __restrict__ oF)
{
    extern __shared__ __align__(1024) char smem[];
    const uint32_t sb = smem_to_u32(smem);
    const int tid  = threadIdx.x;
    const int w    = tid >> 5;
    const int lane = tid & 31;
    const int qt   = (gridDim.x - 1) - blockIdx.x;
    const int bh   = blockIdx.y;
    const int b    = bh >> 4;
    const int h    = bh & 15;
    const int kvh  = h >> 2;

    const size_t qoff = ((size_t)bh * T_SEQ + (size_t)qt * 128) * HD;
    const size_t koff = (size_t)(b * N_KV + kvh) * T_SEQ * HD;

    const int r4 = lane >> 2;
    const int lrow = (lane & 7) + ((lane >> 3) & 1) * 8;
    const int lhi  = lane >> 4;

    #pragma unroll
    for (int j = 0; j < 8; j++) {
        int i = tid + j * 256;
        int row = i >> 4, cb = i & 15;
        cp16(sb + ATT_Q + swz256(row, cb),
             (const char*)qf + (qoff + (size_t)row * HD) * 2 + cb * 16);
    }
    asm volatile("cp.async.commit_group;\n");

    auto load_stage = [&](int kt) {
        uint32_t st = sb + ATT_ST0 + (uint32_t)(kt % 3) * ATT_STAGE;
        size_t base = (koff + (size_t)kt * 128 * HD) * 2;
        #pragma unroll
        for (int j = 0; j < 8; j++) {
            int i = tid + j * 256;
            int row = i >> 4, cb = i & 15;
            uint32_t so = swz256(row, cb);
            size_t go = base + (size_t)row * 256 + cb * 16;
            cp16(st + ATT_K + so, (const char*)kf + go);
            cp16(st + ATT_V + so, (const char*)vf + go);
        }
        asm volatile("cp.async.commit_group;\n");
    };

    const int nkt = qt + 1;
    load_stage(0);
    if (nkt > 1) load_stage(1);

    float acc[16][4];
    #pragma unroll
    for (int nt = 0; nt < 16; nt++)
        #pragma unroll
        for (int i = 0; i < 4; i++) acc[nt][i] = 0.f;
    float m0 = -1e30f, m1 = -1e30f, l0 = 0.f, l1 = 0.f;

    const int qrow0 = qt * 128 + 16 * w + r4;
    const uint32_t qbase = (uint32_t)((16 * w + lrow) * 256);
    const uint32_t krow  = (uint32_t)(lrow * 256);
    const int rmask = lrow & 7;

    for (int kt = 0; kt < nkt; kt++) {
        if (kt == nkt - 1) asm volatile("cp.async.wait_group 0;\n");
        else               asm volatile("cp.async.wait_group 1;\n");
        __syncthreads();
        if (kt + 2 < nkt) load_stage(kt + 2);

        int kvbase = kt * 128;
        uint32_t st = sb + ATT_ST0 + (uint32_t)(kt % 3) * ATT_STAGE;

        float sacc[16][4];
        #pragma unroll
        for (int nt = 0; nt < 16; nt++)
            #pragma unroll
            for (int i = 0; i < 4; i++) sacc[nt][i] = 0.f;

        #pragma unroll
        for (int ks = 0; ks < 8; ks++) {
            int cb = 2 * ks + lhi;
            uint32_t q4[4];
            LDSM_X4(q4, sb + ATT_Q + qbase + ((uint32_t)(cb ^ rmask) << 4));
            #pragma unroll
            for (int nt2 = 0; nt2 < 8; nt2++) {
                uint32_t k4[4];
                LDSM_X4(k4, st + ATT_K + krow + nt2 * 4096 + ((uint32_t)(cb ^ rmask) << 4));
                MMA16816(sacc[2*nt2],   q4, k4[0], k4[2]);
                MMA16816(sacc[2*nt2+1], q4, k4[1], k4[3]);
            }
        }

        if (kvbase + 127 > qrow0) {
            #pragma unroll
            for (int nt = 0; nt < 16; nt++) {
                int col = kvbase + 8 * nt + (lane & 3) * 2;
                if (col     > qrow0)     sacc[nt][0] = -1e30f;
                if (col + 1 > qrow0)     sacc[nt][1] = -1e30f;
                if (col     > qrow0 + 8) sacc[nt][2] = -1e30f;
                if (col + 1 > qrow0 + 8) sacc[nt][3] = -1e30f;
            }
        }

        float ml0 = -1e30f, ml1 = -1e30f;
        #pragma unroll
        for (int nt = 0; nt < 16; nt++) {
            ml0 = fmaxf(ml0, fmaxf(sacc[nt][0], sacc[nt][1]));
            ml1 = fmaxf(ml1, fmaxf(sacc[nt][2], sacc[nt][3]));
        }
        ml0 = fmaxf(ml0, __shfl_xor_sync(0xffffffffu, ml0, 1));
        ml0 = fmaxf(ml0, __shfl_xor_sync(0xffffffffu, ml0, 2));
        ml1 = fmaxf(ml1, __shfl_xor_sync(0xffffffffu, ml1, 1));
        ml1 = fmaxf(ml1, __shfl_xor_sync(0xffffffffu, ml1, 2));
        float mn0 = fmaxf(m0, ml0), mn1 = fmaxf(m1, ml1);
        float c0 = exp2f(m0 - mn0), c1 = exp2f(m1 - mn1);
        float ps0 = 0.f, ps1 = 0.f;
        #pragma unroll
        for (int nt = 0; nt < 16; nt++) {
            sacc[nt][0] = exp2f(sacc[nt][0] - mn0);
            sacc[nt][1] = exp2f(sacc[nt][1] - mn0);
            sacc[nt][2] = exp2f(sacc[nt][2] - mn1);
            sacc[nt][3] = exp2f(sacc[nt][3] - mn1);
            ps0 += sacc[nt][0] + sacc[nt][1];
            ps1 += sacc[nt][2] + sacc[nt][3];
        }
        ps0 += __shfl_xor_sync(0xffffffffu, ps0, 1);
        ps0 += __shfl_xor_sync(0xffffffffu, ps0, 2);
        ps1 += __shfl_xor_sync(0xffffffffu, ps1, 1);
        ps1 += __shfl_xor_sync(0xffffffffu, ps1, 2);
        l0 = l0 * c0 + ps0;
        l1 = l1 * c1 + ps1;
        m0 = mn0; m1 = mn1;
        #pragma unroll
        for (int nt = 0; nt < 16; nt++) {
            acc[nt][0] *= c0; acc[nt][1] *= c0;
            acc[nt][2] *= c1; acc[nt][3] *= c1;
        }

        uint32_t ph[8][4];
        #pragma unroll
        for (int j = 0; j < 8; j++) {
            #pragma unroll
            for (int half = 0; half < 2; half++) {
                ph[j][2*half]   = packh(sacc[2*j+half][0], sacc[2*j+half][1]);
                ph[j][2*half+1] = packh(sacc[2*j+half][2], sacc[2*j+half][3]);
            }
        }

        #pragma unroll
        for (int j = 0; j < 8; j++) {
            uint32_t vrow = st + ATT_V + krow + j * 4096;
            #pragma unroll
            for (int dt = 0; dt < 8; dt++) {
                int cb = 2 * dt + lhi;
                uint32_t v4[4];
                LDSM_X4_T(v4, vrow + ((uint32_t)(cb ^ rmask) << 4));
                MMA16816(acc[2*dt],   ph[j], v4[0], v4[1]);
                MMA16816(acc[2*dt+1], ph[j], v4[2], v4[3]);
            }
        }
    }

    float i0 = 1.f / l0, i1 = 1.f / l1;
    const int trow0 = qt * 128 + 16 * w + r4;
    const size_t orow0 = (size_t)(b * T_SEQ + trow0) * 2048 + h * 128;
    const size_t orow1 = orow0 + 8 * 2048;
    #pragma unroll
    for (int nt = 0; nt < 16; nt++) {
        int d = 8 * nt + (lane & 3) * 2;
        *(uint32_t*)&oF[orow0 + d] = packh(acc[nt][0] * i0, acc[nt][1] * i0);
        *(uint32_t*)&oF[orow1 + d] = packh(acc[nt][2] * i1, acc[nt][3] * i1);
    }
}

// ---------------- launch ----------------
extern "C" void kernel_launch(void* const* d_in, const int* in_sizes, int n_in,
                              void* d_out, int out_size)
{
    const float* x   = (const float*)d_in[0];
    const float* w_q = (const float*)d_in[1];
    const float* w_k = (const float*)d_in[2];
    const float* w_v = (const float*)d_in[3];
    const float* w_o = (const float*)d_in[4];
    float* out = (float*)d_out;

    __half *xF, *wF, *woF, *aF, *qF, *kF, *vF;
    cudaGetSymbolAddress((void**)&xF,  g_xF);
    cudaGetSymbolAddress((void**)&wF,  g_wF);
    cudaGetSymbolAddress((void**)&woF, g_woF);
    cudaGetSymbolAddress((void**)&aF,  g_aF);
    cudaGetSymbolAddress((void**)&qF,  g_qF);
    cudaGetSymbolAddress((void**)&kF,  g_kF);
    cudaGetSymbolAddress((void**)&vF,  g_vF);

    // RoPE cos/sin table + fused input conversion (wq/wk rows permuted)
    rope_table<<<(T_SEQ * 64 + 255) / 256, 256>>>();
    convert_all<<<(CV_WO + 255) / 256, 256>>>(x, w_q, w_k, w_v, w_o, xF, wF, woF);

    cudaFuncSetAttribute(gemm_fp16<0>, cudaFuncAttributeMaxDynamicSharedMemorySize, GEMM_SMEM);
    cudaFuncSetAttribute(gemm_fp16<1>, cudaFuncAttributeMaxDynamicSharedMemorySize, GEMM_SMEM);

    // fused QKV projection + RoPE epilogue -> qF/kF/vF (gridded, 2 CTAs/SM)
    gemm_fp16<1><<<dim3(3072 / 128, MROWS / 128), 256, GEMM_SMEM>>>(xF, wF, nullptr);

    // tensor-core attention (BN=128) -> g_aF
    cudaFuncSetAttribute(attn_mma, cudaFuncAttributeMaxDynamicSharedMemorySize, ATT_SMEM);
    attn_mma<<<dim3(T_SEQ / 128, B_SZ * N_HEADS), 256, ATT_SMEM>>>(qF, kF, vF, aF);

    // O projection (gridded, 2 CTAs/SM)
    gemm_fp16<0><<<dim3(2048 / 128, MROWS / 128), 256, GEMM_SMEM>>>(aF, woF, out);
}

// round 17
// speedup vs baseline: 1.0528x; 1.0080x over previous
#include <cuda_runtime.h>
#include <cuda_fp16.h>
#include <math.h>
#include <stdint.h>

#define B_SZ    2
#define T_SEQ   2048
#define D_MODEL 2048
#define N_HEADS 16
#define N_KV    4
#define HD      128
#define KDIM    2048
#define MROWS   (B_SZ * T_SEQ)          // 4096

#define QSCALE  (0.08838834764831845f * 1.4426950408889634f)

// ---------------- scratch (static device globals; no allocs) ----------------
__device__ __half g_xF[(size_t)MROWS * KDIM];
__device__ __half g_wF[(size_t)3072 * KDIM];    // wq|wk (row-permuted) | wv
__device__ __half g_woF[(size_t)2048 * KDIM];
__device__ __half g_aF[(size_t)MROWS * KDIM];

__device__ __half g_qF[(size_t)B_SZ * N_HEADS * T_SEQ * HD];  // post-RoPE (permuted dims)
__device__ __half g_kF[(size_t)B_SZ * N_KV * T_SEQ * HD];
__device__ __half g_vF[(size_t)B_SZ * N_KV * T_SEQ * HD];
__device__ float2 g_rope[(size_t)T_SEQ * 64];                 // (cos, sin) per (pos, freq)

// ---------------- helpers ----------------
__device__ __forceinline__ uint32_t smem_to_u32(const void* p) {
    uint32_t a;
    asm("{ .reg .u64 t; cvta.to.shared.u64 t, %1; cvt.u32.u64 %0, t; }" : "=r"(a) : "l"(p));
    return a;
}
#define SW128(off) ((off) ^ (((off) >> 3) & 0x70))

__device__ __forceinline__ void cp16(uint32_t saddr, const void* g) {
    asm volatile("cp.async.cg.shared.global [%0], [%1], 16;\n" :: "r"(saddr), "l"(g));
}
#define LDSM_X4(r, a) \
    asm volatile("ldmatrix.sync.aligned.m8n8.x4.shared.b16 {%0,%1,%2,%3}, [%4];" \
        : "=r"((r)[0]), "=r"((r)[1]), "=r"((r)[2]), "=r"((r)[3]) : "r"(a))
#define LDSM_X4_T(r, a) \
    asm volatile("ldmatrix.sync.aligned.m8n8.x4.trans.shared.b16 {%0,%1,%2,%3}, [%4];" \
        : "=r"((r)[0]), "=r"((r)[1]), "=r"((r)[2]), "=r"((r)[3]) : "r"(a))
#define MMA16816(c, a, b0, b1) \
    asm volatile("mma.sync.aligned.m16n8k16.row.col.f32.f16.f16.f32 " \
        "{%0,%1,%2,%3}, {%4,%5,%6,%7}, {%8,%9}, {%0,%1,%2,%3};" \
        : "+f"((c)[0]), "+f"((c)[1]), "+f"((c)[2]), "+f"((c)[3]) \
        : "r"((a)[0]), "r"((a)[1]), "r"((a)[2]), "r"((a)[3]), "r"(b0), "r"(b1))

__device__ __forceinline__ uint32_t packh(float a, float b) {
    __half2 t = __floats2half2_rn(a, b);
    return reinterpret_cast<uint32_t&>(t);
}

// ---------------- fused conversion + rope table (one kernel) -----------
// Permutation: within each head, out-dim pairs (2j, 2j+1) = orig (j, j+64).
#define CV_X   2097152                       // float4 counts
#define CV_WQ  (CV_X  + 1048576)
#define CV_WK  (CV_WQ + 262144)
#define CV_WV  (CV_WK + 262144)
#define CV_WO  (CV_WV + 1048576)             // 4718592 total
#define CV_RT  (CV_WO + T_SEQ * 64)          // rope-table tail

__global__ void convert_all(const float* __restrict__ x,  const float* __restrict__ wq,
                            const float* __restrict__ wk, const float* __restrict__ wv,
                            const float* __restrict__ wo,
                            __half* __restrict__ xF, __half* __restrict__ wF,
                            __half* __restrict__ woF)
{
    int i = blockIdx.x * blockDim.x + threadIdx.x;
    if (i >= CV_RT) return;
    if (i >= CV_WO) {                          // rope table entries
        int idx = i - CV_WO;
        int tq = idx >> 6, j = idx & 63;
        float inv = __expf(-((float)j / 64.0f) * 13.815510557964274f);
        float s, c;
        sincosf((float)tq * inv, &s, &c);
        g_rope[idx] = make_float2(c, s);
        return;
    }
    const float* src; __half* dst; int off; int doff;
    if      (i < CV_X)  { src = x;  dst = xF;  off = i; doff = off; }
    else if (i < CV_WQ) {
        src = wq; dst = wF; off = i - CV_X;
        int row = off >> 9, cin = off & 511;
        int j = row & 127;
        int pj = (j < 64) ? (2 * j) : (2 * (j - 64) + 1);
        doff = (((row & ~127) | pj) << 9) | cin;
    }
    else if (i < CV_WK) {
        src = wk; dst = wF + (size_t)2048 * KDIM; off = i - CV_WQ;
        int row = off >> 9, cin = off & 511;
        int j = row & 127;
        int pj = (j < 64) ? (2 * j) : (2 * (j - 64) + 1);
        doff = (((row & ~127) | pj) << 9) | cin;
    }
    else if (i < CV_WV) { src = wv; dst = wF + (size_t)2560 * KDIM; off = i - CV_WK; doff = off; }
    else                { src = wo; dst = woF; off = i - CV_WV; doff = off; }
    float4 v = ((const float4*)src)[off];
    ((__half2*)dst)[2 * doff]     = __floats2half2_rn(v.x, v.y);
    ((__half2*)dst)[2 * doff + 1] = __floats2half2_rn(v.z, v.w);
}

// ---------------- fp16 GEMM: C = A @ B^T, tile 128x128, 2 CTAs/SM ----------------
// MODE 0: C row-major fp32 (N=2048). MODE 1: QKV scatter + fused RoPE -> qF/kF/vF.
#define OFF_A  0
#define OFF_B  16384
#define STAGE_BYTES 32768
#define GEMM_SMEM (3 * STAGE_BYTES)     // 98304

template<int MODE>
__global__ __launch_bounds__(256, 2)
void gemm_fp16(const __half* __restrict__ Af, const __half* __restrict__ Bf,
               float* __restrict__ C)
{
    extern __shared__ __align__(1024) char smem[];
    const uint32_t sb = smem_to_u32(smem);
    const int tid  = threadIdx.x;
    const int lane = tid & 31;
    const int wid  = tid >> 5;
    const int warp_m = (wid & 3) * 32;
    const int warp_n = (wid >> 2) * 64;
    const int bm0 = blockIdx.y * 128;
    const int bn0 = blockIdx.x * 128;

    float acc[2][8][4];
    #pragma unroll
    for (int mt = 0; mt < 2; mt++)
        #pragma unroll
        for (int nt = 0; nt < 8; nt++)
            #pragma unroll
            for (int i = 0; i < 4; i++) acc[mt][nt][i] = 0.f;

    auto load_chunk = [&](int c) {
        uint32_t st = sb + (uint32_t)(c % 3) * STAGE_BYTES;
        int k0 = c * 64;
        #pragma unroll
        for (int j = 0; j < 4; j++) {
            int i = tid + j * 256;
            int row = i >> 3, cb = (i & 7) * 16;
            uint32_t so = SW128((uint32_t)(row * 128 + cb));
            cp16(st + OFF_A + so, (const char*)Af + ((size_t)(bm0 + row) * KDIM + k0) * 2 + cb);
            cp16(st + OFF_B + so, (const char*)Bf + ((size_t)(bn0 + row) * KDIM + k0) * 2 + cb);
        }
        asm volatile("cp.async.commit_group;\n");
    };

    load_chunk(0);
    load_chunk(1);

    const int lrow = (lane & 7) + ((lane >> 3) & 1) * 8;
    const uint32_t abase = (uint32_t)((warp_m + lrow) * 128);
    const uint32_t bbase = (uint32_t)((warp_n + lrow) * 128);

    const int NC = KDIM / 64;
    for (int c = 0; c < NC; c++) {
        if (c == NC - 1) asm volatile("cp.async.wait_group 0;\n");
        else             asm volatile("cp.async.wait_group 1;\n");
        __syncthreads();
        if (c + 2 < NC) load_chunk(c + 2);

        uint32_t st = sb + (uint32_t)(c % 3) * STAGE_BYTES;
        #pragma unroll
        for (int ks = 0; ks < 4; ks++) {
            uint32_t ah[2][4], bh[4][4];
            int lcb = ks * 32 + (lane >> 4) * 16;
            #pragma unroll
            for (int mt = 0; mt < 2; mt++)
                LDSM_X4(ah[mt], st + OFF_A + SW128(abase + mt * 2048 + lcb));
            #pragma unroll
            for (int nt = 0; nt < 4; nt++)
                LDSM_X4(bh[nt], st + OFF_B + SW128(bbase + nt * 2048 + lcb));
            #pragma unroll
            for (int mt = 0; mt < 2; mt++) {
                #pragma unroll
                for (int nt4 = 0; nt4 < 4; nt4++) {
                    MMA16816(acc[mt][2*nt4],   ah[mt], bh[nt4][0], bh[nt4][2]);
                    MMA16816(acc[mt][2*nt4+1], ah[mt], bh[nt4][1], bh[nt4][3]);
                }
            }
        }
    }

    const int rbase = bm0 + warp_m + (lane >> 2);
    const int cbase = bn0 + warp_n + (lane & 3) * 2;
    #pragma unroll
    for (int mt = 0; mt < 2; mt++) {
        #pragma unroll
        for (int hh = 0; hh < 2; hh++) {
            int row = rbase + mt * 16 + hh * 8;
            #pragma unroll
            for (int nt = 0; nt < 8; nt++) {
                int col = cbase + nt * 8;
                float2 v = make_float2(acc[mt][nt][2*hh], acc[mt][nt][2*hh+1]);
                if (MODE == 0) {
                    *(float2*)&C[(size_t)row * 2048 + col] = v;
                } else {
                    int b = row >> 11, tq = row & (T_SEQ - 1), d = col & 127;
                    if (col < 2048) {
                        int h = col >> 7;
                        float2 cs = g_rope[tq * 64 + (d >> 1)];
                        float o1 = (v.x * cs.x - v.y * cs.y) * QSCALE;
                        float o2 = (v.y * cs.x + v.x * cs.y) * QSCALE;
                        *(uint32_t*)(g_qF + (((size_t)(b * N_HEADS + h) * T_SEQ + tq) * HD + d)) = packh(o1, o2);
                    } else if (col < 2560) {
                        int h = (col - 2048) >> 7;
                        float2 cs = g_rope[tq * 64 + (d >> 1)];
                        float o1 = v.x * cs.x - v.y * cs.y;
                        float o2 = v.y * cs.x + v.x * cs.y;
                        *(uint32_t*)(g_kF + (((size_t)(b * N_KV + h) * T_SEQ + tq) * HD + d)) = packh(o1, o2);
                    } else {
                        int h = (col - 2560) >> 7;
                        *(uint32_t*)(g_vF + (((size_t)(b * N_KV + h) * T_SEQ + tq) * HD + d)) = packh(v.x, v.y);
                    }
                }
            }
        }
    }
}

// ---------------- tensor-core flash attention (fp16, BN=128, base-2 softmax) ------
// K and V fragments double-buffered to break the LDSM->MMA RAW chain.
#define ATT_Q 0
#define ATT_ST0 32768
#define ATT_STAGE 65536
#define ATT_K 0
#define ATT_V 32768
#define ATT_SMEM (ATT_ST0 + 3 * ATT_STAGE)   // 229376

__device__ __forceinline__ uint32_t swz256(int row, int cb) {
    return (uint32_t)(row * 256 + ((cb ^ (row & 7)) << 4));
}

__global__ __launch_bounds__(256, 1)
void attn_mma(const __half* __restrict__ qf, const __half* __restrict__ kf,
              const __half* __restrict__ vf, __half* __restrict__ oF)
{
    extern __shared__ __align__(1024) char smem[];
    const uint32_t sb = smem_to_u32(smem);
    const int tid  = threadIdx.x;
    const int w    = tid >> 5;
    const int lane = tid & 31;
    const int qt   = (gridDim.x - 1) - blockIdx.x;
    const int bh   = blockIdx.y;
    const int b    = bh >> 4;
    const int h    = bh & 15;
    const int kvh  = h >> 2;

    const size_t qoff = ((size_t)bh * T_SEQ + (size_t)qt * 128) * HD;
    const size_t koff = (size_t)(b * N_KV + kvh) * T_SEQ * HD;

    const int r4 = lane >> 2;
    const int lrow = (lane & 7) + ((lane >> 3) & 1) * 8;
    const int lhi  = lane >> 4;

    #pragma unroll
    for (int j = 0; j < 8; j++) {
        int i = tid + j * 256;
        int row = i >> 4, cb = i & 15;
        cp16(sb + ATT_Q + swz256(row, cb),
             (const char*)qf + (qoff + (size_t)row * HD) * 2 + cb * 16);
    }
    asm volatile("cp.async.commit_group;\n");

    auto load_stage = [&](int kt) {
        uint32_t st = sb + ATT_ST0 + (uint32_t)(kt % 3) * ATT_STAGE;
        size_t base = (koff + (size_t)kt * 128 * HD) * 2;
        #pragma unroll
        for (int j = 0; j < 8; j++) {
            int i = tid + j * 256;
            int row = i >> 4, cb = i & 15;
            uint32_t so = swz256(row, cb);
            size_t go = base + (size_t)row * 256 + cb * 16;
            cp16(st + ATT_K + so, (const char*)kf + go);
            cp16(st + ATT_V + so, (const char*)vf + go);
        }
        asm volatile("cp.async.commit_group;\n");
    };

    const int nkt = qt + 1;
    load_stage(0);
    if (nkt > 1) load_stage(1);

    float acc[16][4];
    #pragma unroll
    for (int nt = 0; nt < 16; nt++)
        #pragma unroll
        for (int i = 0; i < 4; i++) acc[nt][i] = 0.f;
    float m0 = -1e30f, m1 = -1e30f, l0 = 0.f, l1 = 0.f;

    const int qrow0 = qt * 128 + 16 * w + r4;
    const uint32_t qbase = (uint32_t)((16 * w + lrow) * 256);
    const uint32_t krow  = (uint32_t)(lrow * 256);
    const int rmask = lrow & 7;

    for (int kt = 0; kt < nkt; kt++) {
        if (kt == nkt - 1) asm volatile("cp.async.wait_group 0;\n");
        else               asm volatile("cp.async.wait_group 1;\n");
        __syncthreads();
        if (kt + 2 < nkt) load_stage(kt + 2);

        int kvbase = kt * 128;
        uint32_t st = sb + ATT_ST0 + (uint32_t)(kt % 3) * ATT_STAGE;

        float sacc[16][4];
        #pragma unroll
        for (int nt = 0; nt < 16; nt++)
            #pragma unroll
            for (int i = 0; i < 4; i++) sacc[nt][i] = 0.f;

        // ---- S = Q K^T : K fragments double-buffered ----
        #pragma unroll
        for (int ks = 0; ks < 8; ks++) {
            int cb = 2 * ks + lhi;
            uint32_t csw = (uint32_t)(cb ^ rmask) << 4;
            uint32_t q4[4];
            LDSM_X4(q4, sb + ATT_Q + qbase + csw);
            uint32_t k4[2][4];
            LDSM_X4(k4[0], st + ATT_K + krow + csw);
            #pragma unroll
            for (int nt2 = 0; nt2 < 8; nt2++) {
                if (nt2 < 7)
                    LDSM_X4(k4[(nt2 + 1) & 1], st + ATT_K + krow + (nt2 + 1) * 4096 + csw);
                MMA16816(sacc[2*nt2],   q4, k4[nt2 & 1][0], k4[nt2 & 1][2]);
                MMA16816(sacc[2*nt2+1], q4, k4[nt2 & 1][1], k4[nt2 & 1][3]);
            }
        }

        if (kvbase + 127 > qrow0) {
            #pragma unroll
            for (int nt = 0; nt < 16; nt++) {
                int col = kvbase + 8 * nt + (lane & 3) * 2;
                if (col     > qrow0)     sacc[nt][0] = -1e30f;
                if (col + 1 > qrow0)     sacc[nt][1] = -1e30f;
                if (col     > qrow0 + 8) sacc[nt][2] = -1e30f;
                if (col + 1 > qrow0 + 8) sacc[nt][3] = -1e30f;
            }
        }

        float ml0 = -1e30f, ml1 = -1e30f;
        #pragma unroll
        for (int nt = 0; nt < 16; nt++) {
            ml0 = fmaxf(ml0, fmaxf(sacc[nt][0], sacc[nt][1]));
            ml1 = fmaxf(ml1, fmaxf(sacc[nt][2], sacc[nt][3]));
        }
        ml0 = fmaxf(ml0, __shfl_xor_sync(0xffffffffu, ml0, 1));
        ml0 = fmaxf(ml0, __shfl_xor_sync(0xffffffffu, ml0, 2));
        ml1 = fmaxf(ml1, __shfl_xor_sync(0xffffffffu, ml1, 1));
        ml1 = fmaxf(ml1, __shfl_xor_sync(0xffffffffu, ml1, 2));
        float mn0 = fmaxf(m0, ml0), mn1 = fmaxf(m1, ml1);
        float c0 = exp2f(m0 - mn0), c1 = exp2f(m1 - mn1);
        float ps0 = 0.f, ps1 = 0.f;
        #pragma unroll
        for (int nt = 0; nt < 16; nt++) {
            sacc[nt][0] = exp2f(sacc[nt][0] - mn0);
            sacc[nt][1] = exp2f(sacc[nt][1] - mn0);
            sacc[nt][2] = exp2f(sacc[nt][2] - mn1);
            sacc[nt][3] = exp2f(sacc[nt][3] - mn1);
            ps0 += sacc[nt][0] + sacc[nt][1];
            ps1 += sacc[nt][2] + sacc[nt][3];
        }
        ps0 += __shfl_xor_sync(0xffffffffu, ps0, 1);
        ps0 += __shfl_xor_sync(0xffffffffu, ps0, 2);
        ps1 += __shfl_xor_sync(0xffffffffu, ps1, 1);
        ps1 += __shfl_xor_sync(0xffffffffu, ps1, 2);
        l0 = l0 * c0 + ps0;
        l1 = l1 * c1 + ps1;
        m0 = mn0; m1 = mn1;
        #pragma unroll
        for (int nt = 0; nt < 16; nt++) {
            acc[nt][0] *= c0; acc[nt][1] *= c0;
            acc[nt][2] *= c1; acc[nt][3] *= c1;
        }

        uint32_t ph[8][4];
        #pragma unroll
        for (int j = 0; j < 8; j++) {
            #pragma unroll
            for (int half = 0; half < 2; half++) {
                ph[j][2*half]   = packh(sacc[2*j+half][0], sacc[2*j+half][1]);
                ph[j][2*half+1] = packh(sacc[2*j+half][2], sacc[2*j+half][3]);
            }
        }

        // ---- O += P V : V fragments double-buffered ----
        #pragma unroll
        for (int j = 0; j < 8; j++) {
            uint32_t vrow = st + ATT_V + krow + j * 4096;
            uint32_t v4[2][4];
            LDSM_X4_T(v4[0], vrow + ((uint32_t)(lhi ^ rmask) << 4));
            #pragma unroll
            for (int dt = 0; dt < 8; dt++) {
                if (dt < 7) {
                    int cbn = 2 * (dt + 1) + lhi;
                    LDSM_X4_T(v4[(dt + 1) & 1], vrow + ((uint32_t)(cbn ^ rmask) << 4));
                }
                MMA16816(acc[2*dt],   ph[j], v4[dt & 1][0], v4[dt & 1][1]);
                MMA16816(acc[2*dt+1], ph[j], v4[dt & 1][2], v4[dt & 1][3]);
            }
        }
    }

    float i0 = 1.f / l0, i1 = 1.f / l1;
    const int trow0 = qt * 128 + 16 * w + r4;
    const size_t orow0 = (size_t)(b * T_SEQ + trow0) * 2048 + h * 128;
    const size_t orow1 = orow0 + 8 * 2048;
    #pragma unroll
    for (int nt = 0; nt < 16; nt++) {
        int d = 8 * nt + (lane & 3) * 2;
        *(uint32_t*)&oF[orow0 + d] = packh(acc[nt][0] * i0, acc[nt][1] * i0);
        *(uint32_t*)&oF[orow1 + d] = packh(acc[nt][2] * i1, acc[nt][3] * i1);
    }
}

// ---------------- launch ----------------
extern "C" void kernel_launch(void* const* d_in, const int* in_sizes, int n_in,
                              void* d_out, int out_size)
{
    const float* x   = (const float*)d_in[0];
    const float* w_q = (const float*)d_in[1];
    const float* w_k = (const float*)d_in[2];
    const float* w_v = (const float*)d_in[3];
    const float* w_o = (const float*)d_in[4];
    float* out = (float*)d_out;

    __half *xF, *wF, *woF, *aF, *qF, *kF, *vF;
    cudaGetSymbolAddress((void**)&xF,  g_xF);
    cudaGetSymbolAddress((void**)&wF,  g_wF);
    cudaGetSymbolAddress((void**)&woF, g_woF);
    cudaGetSymbolAddress((void**)&aF,  g_aF);
    cudaGetSymbolAddress((void**)&qF,  g_qF);
    cudaGetSymbolAddress((void**)&kF,  g_kF);
    cudaGetSymbolAddress((void**)&vF,  g_vF);

    // fused input conversion + rope table (one kernel)
    convert_all<<<(CV_RT + 255) / 256, 256>>>(x, w_q, w_k, w_v, w_o, xF, wF, woF);

    cudaFuncSetAttribute(gemm_fp16<0>, cudaFuncAttributeMaxDynamicSharedMemorySize, GEMM_SMEM);
    cudaFuncSetAttribute(gemm_fp16<1>, cudaFuncAttributeMaxDynamicSharedMemorySize, GEMM_SMEM);

    // fused QKV projection + RoPE epilogue -> qF/kF/vF (gridded, 2 CTAs/SM)
    gemm_fp16<1><<<dim3(3072 / 128, MROWS / 128), 256, GEMM_SMEM>>>(xF, wF, nullptr);

    // tensor-core attention (BN=128) -> g_aF
    cudaFuncSetAttribute(attn_mma, cudaFuncAttributeMaxDynamicSharedMemorySize, ATT_SMEM);
    attn_mma<<<dim3(T_SEQ / 128, B_SZ * N_HEADS), 256, ATT_SMEM>>>(qF, kF, vF, aF);

    // O projection (gridded, 2 CTAs/SM)
    gemm_fp16<0><<<dim3(2048 / 128, MROWS / 128), 256, GEMM_SMEM>>>(aF, woF, out);
}